// round 1
// baseline (speedup 1.0000x reference)
#include <cuda_runtime.h>
#include <cstdint>

#define FNUM 64
#define DEG 16
#define KDEG 5

// Packed (feature-pair interleaved), sign-folded, pre-normalized parameters.
__device__ float2 g_pw[DEG][FNUM / 2];       // LCU weights: sigma_k * w[f][k] / sum|w[f][:]|
__device__ float2 g_pc[KDEG + 1][FNUM / 2];  // KAN coeffs: sigma_j * c[f][j]

// ---------------------------------------------------------------------------
// Prep kernel: runs once per launch (tiny). Normalizes LCU weights by the
// per-feature L1 norm, folds the alternating-multiplier sign pattern
// sigma_k = +1 if k mod 4 in {1,2} else -1 into the weights, and interleaves
// features pairwise so the main kernel can load them as 64-bit packed values.
// ---------------------------------------------------------------------------
__global__ void prep_kernel(const float* __restrict__ w, const float* __restrict__ kc) {
    int f = threadIdx.x;
    if (f >= FNUM) return;
    float wv[DEG];
    float den = 0.f;
#pragma unroll
    for (int k = 0; k < DEG; k++) { wv[k] = w[f * DEG + k]; den += fabsf(wv[k]); }
    float inv = 1.f / den;
#pragma unroll
    for (int k = 1; k <= DEG; k++) {
        int m = k & 3;
        float s = (m == 1 || m == 2) ? 1.f : -1.f;
        reinterpret_cast<float*>(g_pw[k - 1])[f] = s * wv[k - 1] * inv;
    }
#pragma unroll
    for (int j = 0; j <= KDEG; j++) {
        int m = j & 3;
        float s = (j <= 2) ? 1.f : ((m == 1 || m == 2) ? 1.f : -1.f);
        reinterpret_cast<float*>(g_pc[j])[f] = s * kc[f * (KDEG + 1) + j];
    }
}

// ---------------------------------------------------------------------------
// Packed f32x2 helpers (Blackwell fma.rn.f32x2 — ptxas never auto-fuses this)
// ---------------------------------------------------------------------------
typedef unsigned long long u64;

__device__ __forceinline__ u64 pk2(float a, float b) {
    u64 r; asm("mov.b64 %0,{%1,%2};" : "=l"(r) : "f"(a), "f"(b)); return r;
}
__device__ __forceinline__ float2 unpk2(u64 v) {
    float2 r; asm("mov.b64 {%0,%1},%2;" : "=f"(r.x), "=f"(r.y) : "l"(v)); return r;
}
__device__ __forceinline__ u64 ffma2(u64 a, u64 b, u64 c) {
    u64 d; asm("fma.rn.f32x2 %0,%1,%2,%3;" : "=l"(d) : "l"(a), "l"(b), "l"(c)); return d;
}
__device__ __forceinline__ u64 fadd2(u64 a, u64 b) {
    u64 d; asm("add.rn.f32x2 %0,%1,%2;" : "=l"(d) : "l"(a), "l"(b)); return d;
}
__device__ __forceinline__ u64 fmul2(u64 a, u64 b) {
    u64 d; asm("mul.rn.f32x2 %0,%1,%2;" : "=l"(d) : "l"(a), "l"(b)); return d;
}

// ---------------------------------------------------------------------------
// Main kernel: one warp per batch row. Each lane owns feature pair (2l, 2l+1)
// packed in one f32x2. Chebyshev recurrences run with alternating +-2x
// multipliers so no per-step negation is needed (signs pre-folded into the
// weights). Persistent grid-stride loop amortizes the register-cached
// parameter loads over many rows; next row's X is prefetched before compute.
// ---------------------------------------------------------------------------
__global__ void __launch_bounds__(256)
qkan_kernel(const float* __restrict__ X, float* __restrict__ out, int Btot) {
    const int lane = threadIdx.x & 31;
    int warp = ((blockIdx.x * blockDim.x) + threadIdx.x) >> 5;
    const int nw = (gridDim.x * blockDim.x) >> 5;

    u64 W[DEG];
    u64 C[KDEG + 1];
#pragma unroll
    for (int k = 0; k < DEG; k++)
        W[k] = *reinterpret_cast<const u64*>(&g_pw[k][lane]);
#pragma unroll
    for (int j = 0; j <= KDEG; j++)
        C[j] = *reinterpret_cast<const u64*>(&g_pc[j][lane]);

    const u64 SGN  = 0x8000000080000000ULL;  // packed sign-flip mask
    const u64 MONE = 0xBF800000BF800000ULL;  // packed (-1.0f, -1.0f)
    const float2* __restrict__ X2 = reinterpret_cast<const float2*>(X);

    int b = warp;
    float2 xv;
    if (b < Btot) xv = __ldg(&X2[(size_t)b * (FNUM / 2) + lane]);

    while (b < Btot) {
        float2 cx = xv;
        int bn = b + nw;
        if (bn < Btot) xv = __ldg(&X2[(size_t)bn * (FNUM / 2) + lane]);  // prefetch

        u64 x   = pk2(cx.x, cx.y);
        u64 x2  = fadd2(x, x);
        u64 nx2 = x2 ^ SGN;

        // ---- QSVT/LCU: sum_k w'_k * sigma_k T_k(x), k = 1..16 ----
        u64 um1 = x;                       // u1 = T1
        u64 acc = fmul2(W[0], x);
        u64 u   = ffma2(x2, x, MONE);      // u2 = T2 = 2x*x - 1
        acc = ffma2(W[1], u, acc);
#pragma unroll
        for (int k = 3; k <= DEG; k++) {
            u64 un = ffma2((k & 1) ? nx2 : x2, u, um1);  // u_k = sigma_k T_k
            acc = ffma2(W[k - 1], un, acc);
            um1 = u; u = un;
        }
        // acc holds packed feat (already /denominator via normalized weights)

        // ---- tanh: z = 1 - 2/(e^{2f}+1). |feat| <= 1 so always accurate. ----
        float2 fe = unpk2(acc);
        float e0 = __expf(2.f * fe.x);
        float e1 = __expf(2.f * fe.y);
        float z0 = 1.f - __fdividef(2.f, e0 + 1.f);
        float z1 = 1.f - __fdividef(2.f, e1 + 1.f);

        // ---- KAN: sum_j c'_j * sigma_j T_j(z), j = 0..5 ----
        u64 z   = pk2(z0, z1);
        u64 z2  = fadd2(z, z);
        u64 nz2 = z2 ^ SGN;
        u64 kum1 = z;
        u64 kacc = ffma2(C[1], z, C[0]);   // c0*T0 + c1*T1
        u64 ku   = ffma2(z2, z, MONE);     // T2
        kacc = ffma2(C[2], ku, kacc);
#pragma unroll
        for (int j = 3; j <= KDEG; j++) {
            u64 kun = ffma2((j & 1) ? nz2 : z2, ku, kum1);
            kacc = ffma2(C[j], kun, kacc);
            kum1 = ku; ku = kun;
        }

        // ---- reduce over 64 features (2 per lane + 5-level butterfly) ----
        float2 pr = unpk2(kacc);
        float s = pr.x + pr.y;
#pragma unroll
        for (int o = 16; o; o >>= 1) s += __shfl_xor_sync(0xffffffffu, s, o);
        if (lane == 0) out[b] = s;

        b = bn;
    }
}

extern "C" void kernel_launch(void* const* d_in, const int* in_sizes, int n_in,
                              void* d_out, int out_size) {
    const float* X  = (const float*)d_in[0];
    const float* w  = (const float*)d_in[1];
    const float* kc = (const float*)d_in[2];
    float* out = (float*)d_out;
    int Btot = in_sizes[0] / FNUM;

    prep_kernel<<<1, FNUM>>>(w, kc);
    // Persistent-style launch: 148 SMs * 3 blocks, 256 threads (8 warps) each.
    qkan_kernel<<<444, 256>>>(X, out, Btot);
}

// round 2
// speedup vs baseline: 1.1385x; 1.1385x over previous
#include <cuda_runtime.h>
#include <cstdint>

#define FNUM 64
#define DEG 16
#define KDEG 5
#define R 4   // rows (batch elements) in flight per warp

// Packed (feature-pair interleaved), sign-folded, pre-normalized parameters.
__device__ float2 g_pw[DEG][FNUM / 2];       // LCU weights: sigma_k * w[f][k] / sum|w[f][:]|
__device__ float2 g_pc[KDEG + 1][FNUM / 2];  // KAN coeffs: sigma_j * c[f][j]

// ---------------------------------------------------------------------------
// Prep kernel (tiny, once per launch): L1-normalize LCU weights, fold the
// alternating-multiplier sign pattern into weights/coeffs, interleave feature
// pairs for packed 64-bit loads.
// ---------------------------------------------------------------------------
__global__ void prep_kernel(const float* __restrict__ w, const float* __restrict__ kc) {
    int f = threadIdx.x;
    if (f >= FNUM) return;
    float wv[DEG];
    float den = 0.f;
#pragma unroll
    for (int k = 0; k < DEG; k++) { wv[k] = w[f * DEG + k]; den += fabsf(wv[k]); }
    float inv = 1.f / den;
#pragma unroll
    for (int k = 1; k <= DEG; k++) {
        int m = k & 3;
        float s = (m == 1 || m == 2) ? 1.f : -1.f;
        reinterpret_cast<float*>(g_pw[k - 1])[f] = s * wv[k - 1] * inv;
    }
#pragma unroll
    for (int j = 0; j <= KDEG; j++) {
        int m = j & 3;
        float s = (j <= 2) ? 1.f : ((m == 1 || m == 2) ? 1.f : -1.f);
        reinterpret_cast<float*>(g_pc[j])[f] = s * kc[f * (KDEG + 1) + j];
    }
}

// ---------------------------------------------------------------------------
// Packed f32x2 helpers (Blackwell fma.rn.f32x2 — PTX only, ptxas won't fuse)
// ---------------------------------------------------------------------------
typedef unsigned long long u64;

__device__ __forceinline__ u64 pk2(float a, float b) {
    u64 r; asm("mov.b64 %0,{%1,%2};" : "=l"(r) : "f"(a), "f"(b)); return r;
}
__device__ __forceinline__ float2 unpk2(u64 v) {
    float2 r; asm("mov.b64 {%0,%1},%2;" : "=f"(r.x), "=f"(r.y) : "l"(v)); return r;
}
__device__ __forceinline__ u64 ffma2(u64 a, u64 b, u64 c) {
    u64 d; asm("fma.rn.f32x2 %0,%1,%2,%3;" : "=l"(d) : "l"(a), "l"(b), "l"(c)); return d;
}
__device__ __forceinline__ u64 fadd2(u64 a, u64 b) {
    u64 d; asm("add.rn.f32x2 %0,%1,%2;" : "=l"(d) : "l"(a), "l"(b)); return d;
}
__device__ __forceinline__ u64 fmul2(u64 a, u64 b) {
    u64 d; asm("mul.rn.f32x2 %0,%1,%2;" : "=l"(d) : "l"(a), "l"(b)); return d;
}

// ---------------------------------------------------------------------------
// Main kernel: each warp owns R=4 batch rows per iteration; lane l holds
// feature pair (2l, 2l+1). The Chebyshev recurrences for the 4 rows are
// interleaved (k-outer, row-inner) so 4 independent dependency chains fill
// the fma pipe; the warp shfl reductions likewise pipeline 4-wide.
// ---------------------------------------------------------------------------
__global__ void __launch_bounds__(256, 2)
qkan_kernel(const float* __restrict__ X, float* __restrict__ out, int Btot) {
    const int lane = threadIdx.x & 31;
    const int warp = ((blockIdx.x * blockDim.x) + threadIdx.x) >> 5;
    const int nw = (gridDim.x * blockDim.x) >> 5;
    const int stride = nw * R;

    u64 W[DEG];
    u64 C[KDEG + 1];
#pragma unroll
    for (int k = 0; k < DEG; k++)
        W[k] = *reinterpret_cast<const u64*>(&g_pw[k][lane]);
#pragma unroll
    for (int j = 0; j <= KDEG; j++)
        C[j] = *reinterpret_cast<const u64*>(&g_pc[j][lane]);

    const u64 SGN  = 0x8000000080000000ULL;  // packed sign-flip mask
    const u64 MONE = 0xBF800000BF800000ULL;  // packed (-1.0f, -1.0f)
    const float2* __restrict__ X2 = reinterpret_cast<const float2*>(X);

    int b = warp * R;
    float2 xv[R];
#pragma unroll
    for (int r = 0; r < R; r++)
        xv[r] = (b + r < Btot) ? __ldg(&X2[(size_t)(b + r) * (FNUM / 2) + lane])
                               : make_float2(0.f, 0.f);

    while (b < Btot) {
        float2 cx[R];
#pragma unroll
        for (int r = 0; r < R; r++) cx[r] = xv[r];
        const int bn = b + stride;
#pragma unroll
        for (int r = 0; r < R; r++)                       // prefetch next tile
            xv[r] = (bn + r < Btot) ? __ldg(&X2[(size_t)(bn + r) * (FNUM / 2) + lane])
                                    : make_float2(0.f, 0.f);

        u64 x2[R], nx2[R], um1[R], u[R], acc[R];
        // ---- QSVT/LCU: sum_k w'_k * sigma_k T_k(x), k = 1..16 ----
#pragma unroll
        for (int r = 0; r < R; r++) {
            u64 x  = pk2(cx[r].x, cx[r].y);
            x2[r]  = fadd2(x, x);
            nx2[r] = x2[r] ^ SGN;
            um1[r] = x;                        // u1 = T1
            acc[r] = fmul2(W[0], x);
            u[r]   = ffma2(x2[r], x, MONE);    // u2 = T2
            acc[r] = ffma2(W[1], u[r], acc[r]);
        }
#pragma unroll
        for (int k = 3; k <= DEG; k++) {
#pragma unroll
            for (int r = 0; r < R; r++) {
                u64 un = ffma2((k & 1) ? nx2[r] : x2[r], u[r], um1[r]);
                acc[r] = ffma2(W[k - 1], un, acc[r]);
                um1[r] = u[r]; u[r] = un;
            }
        }

        // ---- tanh: z = 1 - 2/(e^{2f}+1); |feat| <= 1 so always accurate ----
        u64 z[R];
#pragma unroll
        for (int r = 0; r < R; r++) {
            float2 fe = unpk2(acc[r]);
            float e0 = __expf(2.f * fe.x);
            float e1 = __expf(2.f * fe.y);
            float z0 = 1.f - __fdividef(2.f, e0 + 1.f);
            float z1 = 1.f - __fdividef(2.f, e1 + 1.f);
            z[r] = pk2(z0, z1);
        }

        // ---- KAN: sum_j c'_j * sigma_j T_j(z), j = 0..5 ----
        u64 kacc[R];
#pragma unroll
        for (int r = 0; r < R; r++) {
            x2[r]  = fadd2(z[r], z[r]);
            nx2[r] = x2[r] ^ SGN;
            um1[r] = z[r];
            kacc[r] = ffma2(C[1], z[r], C[0]);
            u[r]   = ffma2(x2[r], z[r], MONE);   // T2
            kacc[r] = ffma2(C[2], u[r], kacc[r]);
        }
#pragma unroll
        for (int j = 3; j <= KDEG; j++) {
#pragma unroll
            for (int r = 0; r < R; r++) {
                u64 un = ffma2((j & 1) ? nx2[r] : x2[r], u[r], um1[r]);
                kacc[r] = ffma2(C[j], un, kacc[r]);
                um1[r] = u[r]; u[r] = un;
            }
        }

        // ---- reduce 64 features: 2 per lane + 5-level butterfly (4-wide) ----
        float s[R];
#pragma unroll
        for (int r = 0; r < R; r++) {
            float2 pr = unpk2(kacc[r]);
            s[r] = pr.x + pr.y;
        }
#pragma unroll
        for (int o = 16; o; o >>= 1)
#pragma unroll
            for (int r = 0; r < R; r++)
                s[r] += __shfl_xor_sync(0xffffffffu, s[r], o);
        if (lane == 0) {
#pragma unroll
            for (int r = 0; r < R; r++)
                if (b + r < Btot) out[b + r] = s[r];
        }

        b = bn;
    }
}

extern "C" void kernel_launch(void* const* d_in, const int* in_sizes, int n_in,
                              void* d_out, int out_size) {
    const float* X  = (const float*)d_in[0];
    const float* w  = (const float*)d_in[1];
    const float* kc = (const float*)d_in[2];
    float* out = (float*)d_out;
    int Btot = in_sizes[0] / FNUM;

    prep_kernel<<<1, FNUM>>>(w, kc);
    // 2 blocks per SM (148 SMs), 8 warps each, 4 rows in flight per warp.
    qkan_kernel<<<296, 256>>>(X, out, Btot);
}